// round 8
// baseline (speedup 1.0000x reference)
#include <cuda_runtime.h>
#include <cstddef>

#define NN 50000
#define NE_MAX 800000
#define FIN 128
#define H1 100
#define H2 200
#define FOUT 16
#define C4_H1 (H1 / 4)   // 25 float4 chunks per row

// -------- scratch (static device globals; no allocation) --------
__device__ __align__(16) int   g_deg[NN];     // edge-only in-degree
__device__ __align__(16) float g_dis[NN];     // (deg+1)^-1/2
__device__ __align__(16) int   g_off[NN];     // CSR range start (arbitrary order)
__device__ __align__(16) int   g_cur[NN];     // fill cursors
__device__               int   g_total;       // global slot cursor
__device__ __align__(16) int   g_src[NE_MAX]; // CSR: source node per slot
__device__ __align__(16) float g_y1 [(size_t)NN * H1];
__device__ __align__(16) float g_y2 [(size_t)NN * H1];
__device__ __align__(16) float g_s2 [(size_t)NN * H1];
__device__ __align__(16) float g_xw2[(size_t)NN * H2];

// ================= degree / CSR build =================
// 4 edges per thread (int4 loads) -> MLP=4 on the atomics.
__global__ void k_count_deg(const int* __restrict__ col, int nE) {
    int q = blockIdx.x * blockDim.x + threadIdx.x;
    int nQ = nE >> 2;
    if (q < nQ) {
        int4 c = *(const int4*)(col + q * 4);
        if ((unsigned)c.x < (unsigned)NN) atomicAdd(&g_deg[c.x], 1);
        if ((unsigned)c.y < (unsigned)NN) atomicAdd(&g_deg[c.y], 1);
        if ((unsigned)c.z < (unsigned)NN) atomicAdd(&g_deg[c.z], 1);
        if ((unsigned)c.w < (unsigned)NN) atomicAdd(&g_deg[c.w], 1);
    } else if (q == nQ) {  // tail
        for (int e = nQ * 4; e < nE; e++) {
            int t = col[e];
            if ((unsigned)t < (unsigned)NN) atomicAdd(&g_deg[t], 1);
        }
    }
}

// dis = (deg+1)^-1/2 ; CSR range via global cursor (order irrelevant)
__global__ void k_assign(int n) {
    int i = blockIdx.x * blockDim.x + threadIdx.x;
    if (i >= n) return;
    int d = g_deg[i];
    g_dis[i] = rsqrtf((float)(d + 1));
    int off = atomicAdd(&g_total, d);
    g_off[i] = off;
    g_cur[i] = off;
}

__global__ void k_fill(const int* __restrict__ row, const int* __restrict__ col, int nE) {
    int q = blockIdx.x * blockDim.x + threadIdx.x;
    int nQ = nE >> 2;
    if (q < nQ) {
        int4 r = *(const int4*)(row + q * 4);
        int4 c = *(const int4*)(col + q * 4);
        int s0 = -1, s1 = -1, s2 = -1, s3 = -1;
        if ((unsigned)c.x < (unsigned)NN && (unsigned)r.x < (unsigned)NN) s0 = atomicAdd(&g_cur[c.x], 1);
        if ((unsigned)c.y < (unsigned)NN && (unsigned)r.y < (unsigned)NN) s1 = atomicAdd(&g_cur[c.y], 1);
        if ((unsigned)c.z < (unsigned)NN && (unsigned)r.z < (unsigned)NN) s2 = atomicAdd(&g_cur[c.z], 1);
        if ((unsigned)c.w < (unsigned)NN && (unsigned)r.w < (unsigned)NN) s3 = atomicAdd(&g_cur[c.w], 1);
        if (s0 >= 0) g_src[s0] = r.x;
        if (s1 >= 0) g_src[s1] = r.y;
        if (s2 >= 0) g_src[s2] = r.z;
        if (s3 >= 0) g_src[s3] = r.w;
    } else if (q == nQ) {  // tail
        for (int e = nQ * 4; e < nE; e++) {
            int rr = row[e], t = col[e];
            if ((unsigned)rr >= (unsigned)NN || (unsigned)t >= (unsigned)NN) continue;
            int slot = atomicAdd(&g_cur[t], 1);
            g_src[slot] = rr;
        }
    }
}

// ================= warp-aligned dense =================
// IN_MODE: 0=plain, 1=relu.  OUT_SCALE: multiply by dis[row].
template <int K, int N, int NJ, int RPW, int WARPS, int IN_MODE, int OUT_SCALE>
__global__ void __launch_bounds__(WARPS * 32)
k_dense_w(const float* __restrict__ in, const float* __restrict__ W,
          const float* __restrict__ bias, float* __restrict__ out, int nRows) {
    constexpr int ROWS = WARPS * RPW;
    constexpr int KV = K / 4;
    __shared__ __align__(16) float s_in[ROWS][K];

    int r0  = blockIdx.x * ROWS;
    int tid = threadIdx.y * 32 + threadIdx.x;
    constexpr int NTH = WARPS * 32;

    const float4* in4 = (const float4*)in;
    for (int i = tid; i < ROWS * KV; i += NTH) {
        int r = i / KV;
        int c = i - r * KV;
        int gr = r0 + r;
        float4 v = make_float4(0.f, 0.f, 0.f, 0.f);
        if (gr < nRows) {
            v = in4[(size_t)gr * KV + c];
            if (IN_MODE == 1) {
                v.x = fmaxf(v.x, 0.f); v.y = fmaxf(v.y, 0.f);
                v.z = fmaxf(v.z, 0.f); v.w = fmaxf(v.w, 0.f);
            }
        }
        *(float4*)&s_in[r][c * 4] = v;
    }
    __syncthreads();

    int lane  = threadIdx.x;
    int rbase = threadIdx.y * RPW;

    float acc[RPW][NJ];
#pragma unroll
    for (int r = 0; r < RPW; r++)
#pragma unroll
        for (int jj = 0; jj < NJ; jj++) acc[r][jj] = 0.f;

#pragma unroll 4
    for (int k0 = 0; k0 < K; k0 += 4) {
        float wr[4][NJ];
#pragma unroll
        for (int kk = 0; kk < 4; kk++)
#pragma unroll
            for (int jj = 0; jj < NJ; jj++) {
                int j = lane + jj * 32;
                wr[kk][jj] = (j < N) ? __ldg(&W[(size_t)(k0 + kk) * N + j]) : 0.f;
            }
#pragma unroll
        for (int r = 0; r < RPW; r++) {
            float4 a = *(const float4*)&s_in[rbase + r][k0];  // warp broadcast
#pragma unroll
            for (int jj = 0; jj < NJ; jj++)
                acc[r][jj] = fmaf(a.x, wr[0][jj], fmaf(a.y, wr[1][jj],
                             fmaf(a.z, wr[2][jj], fmaf(a.w, wr[3][jj], acc[r][jj]))));
        }
    }

    float bv[NJ];
#pragma unroll
    for (int jj = 0; jj < NJ; jj++) {
        int j = lane + jj * 32;
        bv[jj] = (bias != nullptr && j < N) ? __ldg(&bias[j]) : 0.f;
    }
#pragma unroll
    for (int r = 0; r < RPW; r++) {
        int gr = r0 + rbase + r;
        if (gr < nRows) {
            float d = OUT_SCALE ? g_dis[gr] : 1.f;
#pragma unroll
            for (int jj = 0; jj < NJ; jj++) {
                int j = lane + jj * 32;
                if (j < N) out[(size_t)gr * N + j] = (acc[r][jj] + bv[jj]) * d;
            }
        }
    }
}

// ======== old-style dense (FC: N=16 divides warps cleanly) ========
template <int K, int N, int G, int RPB, int IN_MODE>
__global__ void k_dense(const float* __restrict__ in, const float* __restrict__ W,
                        const float* __restrict__ bias, float* __restrict__ out,
                        int nRows) {
    constexpr int ROWS = G * RPB;
    __shared__ __align__(16) float s_in[ROWS][K];

    int r0  = blockIdx.x * ROWS;
    int tid = threadIdx.y * N + threadIdx.x;
    int nth = N * G;

    for (int i = tid; i < ROWS * K; i += nth) {
        int r = i / K;
        int k = i - r * K;
        int gr = r0 + r;
        float v = 0.f;
        if (gr < nRows) {
            v = in[(size_t)gr * K + k];
            if (IN_MODE == 1) v = fmaxf(v, 0.f);
        }
        s_in[r][k] = v;
    }
    __syncthreads();

    int j     = threadIdx.x;
    int rbase = threadIdx.y * RPB;

    float acc[RPB];
#pragma unroll
    for (int r = 0; r < RPB; r++) acc[r] = 0.f;

#pragma unroll 4
    for (int k0 = 0; k0 < K; k0 += 4) {
        float w0 = __ldg(&W[(size_t)(k0 + 0) * N + j]);
        float w1 = __ldg(&W[(size_t)(k0 + 1) * N + j]);
        float w2 = __ldg(&W[(size_t)(k0 + 2) * N + j]);
        float w3 = __ldg(&W[(size_t)(k0 + 3) * N + j]);
#pragma unroll
        for (int r = 0; r < RPB; r++) {
            float4 a = *(const float4*)&s_in[rbase + r][k0];
            acc[r] = fmaf(a.x, w0, fmaf(a.y, w1, fmaf(a.z, w2, fmaf(a.w, w3, acc[r]))));
        }
    }

    float b = (bias != nullptr) ? __ldg(&bias[j]) : 0.f;
#pragma unroll
    for (int r = 0; r < RPB; r++) {
        int gr = r0 + rbase + r;
        if (gr < nRows) out[(size_t)gr * N + j] = acc[r] + b;
    }
}

// ================= CSR gather aggregation (warp per node) =================
// acc = y[node] + sum_{r in neighbors} y[r]  (coalesced row reads; uniform idx loads)
// MODE 1: out = d * relu(d * acc + bias)   (fused mid transform)
// MODE 2: out = d * acc                    (pre-scale for next GEMM)
template <int C4, int MODE>
__global__ void __launch_bounds__(256)
k_gather(const float4* __restrict__ y, const float* __restrict__ bias,
         float4* __restrict__ out, int nN) {
    int node = blockIdx.x * blockDim.y + threadIdx.y;
    if (node >= nN) return;
    int lane  = threadIdx.x;
    int start = g_off[node];
    int cnt   = g_deg[node];
    bool act  = (lane < C4);

    float4 acc = make_float4(0.f, 0.f, 0.f, 0.f);
    if (act) acc = y[(size_t)node * C4 + lane];

    int j = 0;
    for (; j + 8 <= cnt; j += 8) {
        int rr[8];
#pragma unroll
        for (int u = 0; u < 8; u++) rr[u] = __ldg(&g_src[start + j + u]);  // warp-uniform
#pragma unroll
        for (int u = 0; u < 8; u++) {
            if (act) {
                float4 v = __ldg(&y[(size_t)rr[u] * C4 + lane]);
                acc.x += v.x; acc.y += v.y; acc.z += v.z; acc.w += v.w;
            }
        }
    }
    if (j + 4 <= cnt) {
        int rr[4];
#pragma unroll
        for (int u = 0; u < 4; u++) rr[u] = __ldg(&g_src[start + j + u]);
#pragma unroll
        for (int u = 0; u < 4; u++) {
            if (act) {
                float4 v = __ldg(&y[(size_t)rr[u] * C4 + lane]);
                acc.x += v.x; acc.y += v.y; acc.z += v.z; acc.w += v.w;
            }
        }
        j += 4;
    }
    for (; j < cnt; j++) {
        int r = __ldg(&g_src[start + j]);
        if (act) {
            float4 v = __ldg(&y[(size_t)r * C4 + lane]);
            acc.x += v.x; acc.y += v.y; acc.z += v.z; acc.w += v.w;
        }
    }

    if (act) {
        float d = g_dis[node];
        float4 o;
        if (MODE == 1) {
            float4 b = *(const float4*)&bias[lane * 4];
            o.x = d * fmaxf(fmaf(d, acc.x, b.x), 0.f);
            o.y = d * fmaxf(fmaf(d, acc.y, b.y), 0.f);
            o.z = d * fmaxf(fmaf(d, acc.z, b.z), 0.f);
            o.w = d * fmaxf(fmaf(d, acc.w, b.w), 0.f);
        } else {
            o.x = d * acc.x; o.y = d * acc.y; o.z = d * acc.z; o.w = d * acc.w;
        }
        out[(size_t)node * C4 + lane] = o;
    }
}

// ================= launch =================
extern "C" void kernel_launch(void* const* d_in, const int* in_sizes, int n_in,
                              void* d_out, int out_size) {
    const float* x   = (const float*)d_in[0];   // [NN, FIN]
    const int*   ei  = (const int*)d_in[1];     // [2, NE] int32
    const float* W1  = (const float*)d_in[2];
    const float* b1  = (const float*)d_in[3];
    const float* W2  = (const float*)d_in[4];
    const float* b2  = (const float*)d_in[5];
    const float* Wfc = (const float*)d_in[6];
    const float* bfc = (const float*)d_in[7];
    float*       out = (float*)d_out;

    int nN = in_sizes[0] / FIN;
    int nE = in_sizes[1] / 2;
    const int* rowI = ei;
    const int* colI = ei + nE;

    float *p_y1, *p_y2, *p_s2, *p_xw2;
    int   *p_deg, *p_total;
    cudaGetSymbolAddress((void**)&p_y1,   g_y1);
    cudaGetSymbolAddress((void**)&p_y2,   g_y2);
    cudaGetSymbolAddress((void**)&p_s2,   g_s2);
    cudaGetSymbolAddress((void**)&p_xw2,  g_xw2);
    cudaGetSymbolAddress((void**)&p_deg,  g_deg);
    cudaGetSymbolAddress((void**)&p_total, g_total);

    // --- degree + CSR build ---
    cudaMemsetAsync(p_deg, 0, (size_t)nN * sizeof(int));
    cudaMemsetAsync(p_total, 0, sizeof(int));
    {
        int nQ = nE / 4 + 1;  // quad threads + 1 tail thread
        k_count_deg<<<(nQ + 255) / 256, 256>>>(colI, nE);
        k_assign   <<<(nN + 255) / 256, 256>>>(nN);
        k_fill     <<<(nQ + 255) / 256, 256>>>(rowI, colI, nE);
    }

    // --- layer 1: y1 = d_r ⊙ (x @ W1) ---
    k_dense_w<FIN, H1, 4, 8, 8, 0, 1><<<(nN + 63) / 64, dim3(32, 8)>>>(
        x, W1, nullptr, p_y1, nN);

    // --- agg1 + mid fused: y2 = d ⊙ relu(d ⊙ (y1_self + Σ y1[src]) + b1) ---
    k_gather<C4_H1, 1><<<(nN + 7) / 8, dim3(32, 8)>>>(
        (const float4*)p_y1, b1, (float4*)p_y2, nN);

    // --- agg2 (commuted before GEMM): s2 = d ⊙ (y2_self + Σ y2[src]) ---
    k_gather<C4_H1, 2><<<(nN + 7) / 8, dim3(32, 8)>>>(
        (const float4*)p_y2, nullptr, (float4*)p_s2, nN);

    // --- layer 2 GEMM: xw2 = s2 @ W2 + b2 ---
    k_dense_w<H1, H2, 7, 8, 8, 0, 0><<<(nN + 63) / 64, dim3(32, 8)>>>(
        p_s2, W2, b2, p_xw2, nN);

    // --- FC: out = relu(xw2) @ Wfc + bfc ---
    k_dense<H2, FOUT, 8, 4, 1><<<(nN + 31) / 32, dim3(FOUT, 8)>>>(
        p_xw2, Wfc, bfc, out, nN);
}

// round 9
// speedup vs baseline: 1.1587x; 1.1587x over previous
#include <cuda_runtime.h>
#include <cstddef>

#define NN 50000
#define NE_MAX 800000
#define FIN 128
#define H1 100
#define H2 200
#define FOUT 16
#define C4_H1 (H1 / 4)   // 25 float4 chunks per row

// -------- scratch (static device globals; no allocation) --------
__device__ __align__(16) int   g_deg[NN];     // edge-only in-degree
__device__ __align__(16) float g_dis[NN];     // (deg+1)^-1/2
__device__ __align__(16) int   g_off[NN];     // CSR range start (arbitrary order)
__device__ __align__(16) int   g_cur[NN];     // fill cursors
__device__               int   g_total;       // global slot cursor
__device__ __align__(16) int   g_src[NE_MAX]; // CSR: source node per slot
__device__ __align__(16) float g_y1 [(size_t)NN * H1];
__device__ __align__(16) float g_y2 [(size_t)NN * H1];
__device__ __align__(16) float g_s2 [(size_t)NN * H1];
__device__ __align__(16) float g_xw2[(size_t)NN * H2];

// ================= degree / CSR build =================
// 4 edges per thread (int4 loads) -> MLP=4 on the atomics.
__global__ void k_count_deg(const int* __restrict__ col, int nE) {
    int q = blockIdx.x * blockDim.x + threadIdx.x;
    int nQ = nE >> 2;
    if (q < nQ) {
        int4 c = *(const int4*)(col + q * 4);
        if ((unsigned)c.x < (unsigned)NN) atomicAdd(&g_deg[c.x], 1);
        if ((unsigned)c.y < (unsigned)NN) atomicAdd(&g_deg[c.y], 1);
        if ((unsigned)c.z < (unsigned)NN) atomicAdd(&g_deg[c.z], 1);
        if ((unsigned)c.w < (unsigned)NN) atomicAdd(&g_deg[c.w], 1);
    } else if (q == nQ) {  // tail
        for (int e = nQ * 4; e < nE; e++) {
            int t = col[e];
            if ((unsigned)t < (unsigned)NN) atomicAdd(&g_deg[t], 1);
        }
    }
}

// dis = (deg+1)^-1/2 ; CSR range via global cursor (order irrelevant)
__global__ void k_assign(int n) {
    int i = blockIdx.x * blockDim.x + threadIdx.x;
    if (i >= n) return;
    int d = g_deg[i];
    g_dis[i] = rsqrtf((float)(d + 1));
    int off = atomicAdd(&g_total, d);
    g_off[i] = off;
    g_cur[i] = off;
}

__global__ void k_fill(const int* __restrict__ row, const int* __restrict__ col, int nE) {
    int q = blockIdx.x * blockDim.x + threadIdx.x;
    int nQ = nE >> 2;
    if (q < nQ) {
        int4 r = *(const int4*)(row + q * 4);
        int4 c = *(const int4*)(col + q * 4);
        int s0 = -1, s1 = -1, s2 = -1, s3 = -1;
        if ((unsigned)c.x < (unsigned)NN && (unsigned)r.x < (unsigned)NN) s0 = atomicAdd(&g_cur[c.x], 1);
        if ((unsigned)c.y < (unsigned)NN && (unsigned)r.y < (unsigned)NN) s1 = atomicAdd(&g_cur[c.y], 1);
        if ((unsigned)c.z < (unsigned)NN && (unsigned)r.z < (unsigned)NN) s2 = atomicAdd(&g_cur[c.z], 1);
        if ((unsigned)c.w < (unsigned)NN && (unsigned)r.w < (unsigned)NN) s3 = atomicAdd(&g_cur[c.w], 1);
        if (s0 >= 0) g_src[s0] = r.x;
        if (s1 >= 0) g_src[s1] = r.y;
        if (s2 >= 0) g_src[s2] = r.z;
        if (s3 >= 0) g_src[s3] = r.w;
    } else if (q == nQ) {  // tail
        for (int e = nQ * 4; e < nE; e++) {
            int rr = row[e], t = col[e];
            if ((unsigned)rr >= (unsigned)NN || (unsigned)t >= (unsigned)NN) continue;
            int slot = atomicAdd(&g_cur[t], 1);
            g_src[slot] = rr;
        }
    }
}

// ================= warp-aligned dense =================
// IN_MODE: 0=plain, 1=relu.  OUT_SCALE: multiply by dis[row].
template <int K, int N, int NJ, int RPW, int WARPS, int IN_MODE, int OUT_SCALE>
__global__ void __launch_bounds__(WARPS * 32)
k_dense_w(const float* __restrict__ in, const float* __restrict__ W,
          const float* __restrict__ bias, float* __restrict__ out, int nRows) {
    constexpr int ROWS = WARPS * RPW;
    constexpr int KV = K / 4;
    __shared__ __align__(16) float s_in[ROWS][K];

    int r0  = blockIdx.x * ROWS;
    int tid = threadIdx.y * 32 + threadIdx.x;
    constexpr int NTH = WARPS * 32;

    const float4* in4 = (const float4*)in;
    for (int i = tid; i < ROWS * KV; i += NTH) {
        int r = i / KV;
        int c = i - r * KV;
        int gr = r0 + r;
        float4 v = make_float4(0.f, 0.f, 0.f, 0.f);
        if (gr < nRows) {
            v = in4[(size_t)gr * KV + c];
            if (IN_MODE == 1) {
                v.x = fmaxf(v.x, 0.f); v.y = fmaxf(v.y, 0.f);
                v.z = fmaxf(v.z, 0.f); v.w = fmaxf(v.w, 0.f);
            }
        }
        *(float4*)&s_in[r][c * 4] = v;
    }
    __syncthreads();

    int lane  = threadIdx.x;
    int rbase = threadIdx.y * RPW;

    float acc[RPW][NJ];
#pragma unroll
    for (int r = 0; r < RPW; r++)
#pragma unroll
        for (int jj = 0; jj < NJ; jj++) acc[r][jj] = 0.f;

#pragma unroll 2
    for (int k0 = 0; k0 < K; k0 += 4) {
        float wr[4][NJ];
#pragma unroll
        for (int kk = 0; kk < 4; kk++)
#pragma unroll
            for (int jj = 0; jj < NJ; jj++) {
                int j = lane + jj * 32;
                wr[kk][jj] = (j < N) ? __ldg(&W[(size_t)(k0 + kk) * N + j]) : 0.f;
            }
#pragma unroll
        for (int r = 0; r < RPW; r++) {
            float4 a = *(const float4*)&s_in[rbase + r][k0];  // warp broadcast
#pragma unroll
            for (int jj = 0; jj < NJ; jj++)
                acc[r][jj] = fmaf(a.x, wr[0][jj], fmaf(a.y, wr[1][jj],
                             fmaf(a.z, wr[2][jj], fmaf(a.w, wr[3][jj], acc[r][jj]))));
        }
    }

    float bv[NJ];
#pragma unroll
    for (int jj = 0; jj < NJ; jj++) {
        int j = lane + jj * 32;
        bv[jj] = (bias != nullptr && j < N) ? __ldg(&bias[j]) : 0.f;
    }
#pragma unroll
    for (int r = 0; r < RPW; r++) {
        int gr = r0 + rbase + r;
        if (gr < nRows) {
            float d = OUT_SCALE ? g_dis[gr] : 1.f;
#pragma unroll
            for (int jj = 0; jj < NJ; jj++) {
                int j = lane + jj * 32;
                if (j < N) out[(size_t)gr * N + j] = (acc[r][jj] + bv[jj]) * d;
            }
        }
    }
}

// ======== old-style dense (FC: N=16 divides warps cleanly) ========
template <int K, int N, int G, int RPB, int IN_MODE>
__global__ void k_dense(const float* __restrict__ in, const float* __restrict__ W,
                        const float* __restrict__ bias, float* __restrict__ out,
                        int nRows) {
    constexpr int ROWS = G * RPB;
    __shared__ __align__(16) float s_in[ROWS][K];

    int r0  = blockIdx.x * ROWS;
    int tid = threadIdx.y * N + threadIdx.x;
    int nth = N * G;

    for (int i = tid; i < ROWS * K; i += nth) {
        int r = i / K;
        int k = i - r * K;
        int gr = r0 + r;
        float v = 0.f;
        if (gr < nRows) {
            v = in[(size_t)gr * K + k];
            if (IN_MODE == 1) v = fmaxf(v, 0.f);
        }
        s_in[r][k] = v;
    }
    __syncthreads();

    int j     = threadIdx.x;
    int rbase = threadIdx.y * RPB;

    float acc[RPB];
#pragma unroll
    for (int r = 0; r < RPB; r++) acc[r] = 0.f;

#pragma unroll 4
    for (int k0 = 0; k0 < K; k0 += 4) {
        float w0 = __ldg(&W[(size_t)(k0 + 0) * N + j]);
        float w1 = __ldg(&W[(size_t)(k0 + 1) * N + j]);
        float w2 = __ldg(&W[(size_t)(k0 + 2) * N + j]);
        float w3 = __ldg(&W[(size_t)(k0 + 3) * N + j]);
#pragma unroll
        for (int r = 0; r < RPB; r++) {
            float4 a = *(const float4*)&s_in[rbase + r][k0];
            acc[r] = fmaf(a.x, w0, fmaf(a.y, w1, fmaf(a.z, w2, fmaf(a.w, w3, acc[r]))));
        }
    }

    float b = (bias != nullptr) ? __ldg(&bias[j]) : 0.f;
#pragma unroll
    for (int r = 0; r < RPB; r++) {
        int gr = r0 + rbase + r;
        if (gr < nRows) out[(size_t)gr * N + j] = acc[r] + b;
    }
}

// ================= CSR gather aggregation (warp per node) =================
// acc = y[node] + sum_{r in neighbors} y[r]  (coalesced row reads; uniform idx loads)
// MODE 1: out = d * relu(d * acc + bias)   (fused mid transform)
// MODE 2: out = d * acc                    (pre-scale for next GEMM)
template <int C4, int MODE>
__global__ void __launch_bounds__(256)
k_gather(const float4* __restrict__ y, const float* __restrict__ bias,
         float4* __restrict__ out, int nN) {
    int node = blockIdx.x * blockDim.y + threadIdx.y;
    if (node >= nN) return;
    int lane  = threadIdx.x;
    int start = g_off[node];
    int cnt   = g_deg[node];
    bool act  = (lane < C4);

    float4 acc = make_float4(0.f, 0.f, 0.f, 0.f);
    if (act) acc = y[(size_t)node * C4 + lane];

    int j = 0;
    for (; j + 8 <= cnt; j += 8) {
        int rr[8];
#pragma unroll
        for (int u = 0; u < 8; u++) rr[u] = __ldg(&g_src[start + j + u]);  // warp-uniform
#pragma unroll
        for (int u = 0; u < 8; u++) {
            if (act) {
                float4 v = __ldg(&y[(size_t)rr[u] * C4 + lane]);
                acc.x += v.x; acc.y += v.y; acc.z += v.z; acc.w += v.w;
            }
        }
    }
    if (j + 4 <= cnt) {
        int rr[4];
#pragma unroll
        for (int u = 0; u < 4; u++) rr[u] = __ldg(&g_src[start + j + u]);
#pragma unroll
        for (int u = 0; u < 4; u++) {
            if (act) {
                float4 v = __ldg(&y[(size_t)rr[u] * C4 + lane]);
                acc.x += v.x; acc.y += v.y; acc.z += v.z; acc.w += v.w;
            }
        }
        j += 4;
    }
    for (; j < cnt; j++) {
        int r = __ldg(&g_src[start + j]);
        if (act) {
            float4 v = __ldg(&y[(size_t)r * C4 + lane]);
            acc.x += v.x; acc.y += v.y; acc.z += v.z; acc.w += v.w;
        }
    }

    if (act) {
        float d = g_dis[node];
        float4 o;
        if (MODE == 1) {
            float4 b = *(const float4*)&bias[lane * 4];
            o.x = d * fmaxf(fmaf(d, acc.x, b.x), 0.f);
            o.y = d * fmaxf(fmaf(d, acc.y, b.y), 0.f);
            o.z = d * fmaxf(fmaf(d, acc.z, b.z), 0.f);
            o.w = d * fmaxf(fmaf(d, acc.w, b.w), 0.f);
        } else {
            o.x = d * acc.x; o.y = d * acc.y; o.z = d * acc.z; o.w = d * acc.w;
        }
        out[(size_t)node * C4 + lane] = o;
    }
}

// ================= launch =================
extern "C" void kernel_launch(void* const* d_in, const int* in_sizes, int n_in,
                              void* d_out, int out_size) {
    const float* x   = (const float*)d_in[0];   // [NN, FIN]
    const int*   ei  = (const int*)d_in[1];     // [2, NE] int32
    const float* W1  = (const float*)d_in[2];
    const float* b1  = (const float*)d_in[3];
    const float* W2  = (const float*)d_in[4];
    const float* b2  = (const float*)d_in[5];
    const float* Wfc = (const float*)d_in[6];
    const float* bfc = (const float*)d_in[7];
    float*       out = (float*)d_out;

    int nN = in_sizes[0] / FIN;
    int nE = in_sizes[1] / 2;
    const int* rowI = ei;
    const int* colI = ei + nE;

    float *p_y1, *p_y2, *p_s2, *p_xw2;
    int   *p_deg, *p_total;
    cudaGetSymbolAddress((void**)&p_y1,   g_y1);
    cudaGetSymbolAddress((void**)&p_y2,   g_y2);
    cudaGetSymbolAddress((void**)&p_s2,   g_s2);
    cudaGetSymbolAddress((void**)&p_xw2,  g_xw2);
    cudaGetSymbolAddress((void**)&p_deg,  g_deg);
    cudaGetSymbolAddress((void**)&p_total, g_total);

    // --- degree + CSR build ---
    cudaMemsetAsync(p_deg, 0, (size_t)nN * sizeof(int));
    cudaMemsetAsync(p_total, 0, sizeof(int));
    {
        int nQ = nE / 4 + 1;  // quad threads + 1 tail thread
        k_count_deg<<<(nQ + 255) / 256, 256>>>(colI, nE);
        k_assign   <<<(nN + 255) / 256, 256>>>(nN);
        k_fill     <<<(nQ + 255) / 256, 256>>>(rowI, colI, nE);
    }

    // --- layer 1: y1 = d_r ⊙ (x @ W1) ---
    k_dense_w<FIN, H1, 4, 8, 8, 0, 1><<<(nN + 63) / 64, dim3(32, 8)>>>(
        x, W1, nullptr, p_y1, nN);

    // --- agg1 + mid fused: y2 = d ⊙ relu(d ⊙ (y1_self + Σ y1[src]) + b1) ---
    k_gather<C4_H1, 1><<<(nN + 7) / 8, dim3(32, 8)>>>(
        (const float4*)p_y1, b1, (float4*)p_y2, nN);

    // --- agg2 (commuted before GEMM): s2 = d ⊙ (y2_self + Σ y2[src]) ---
    k_gather<C4_H1, 2><<<(nN + 7) / 8, dim3(32, 8)>>>(
        (const float4*)p_y2, nullptr, (float4*)p_s2, nN);

    // --- layer 2 GEMM: xw2 = s2 @ W2 + b2 ---
    k_dense_w<H1, H2, 7, 8, 8, 0, 0><<<(nN + 63) / 64, dim3(32, 8)>>>(
        p_s2, W2, b2, p_xw2, nN);

    // --- FC: out = relu(xw2) @ Wfc + bfc ---
    k_dense<H2, FOUT, 8, 4, 1><<<(nN + 31) / 32, dim3(FOUT, 8)>>>(
        p_xw2, Wfc, bfc, out, nN);
}